// round 3
// baseline (speedup 1.0000x reference)
#include <cuda_runtime.h>
#include <math.h>

// Problem dims
#define NB   4
#define NL   2048
#define ND   1024
#define NH   4096
#define NV   32000
#define NEXP 16
#define NTOK (NB*NL)     // 8192 tokens
#define KCAT (2*NH)      // 8192: concatenated hidden of the two selected experts

// ---------------- scratch (device globals: no allocation in kernel_launch) --
__device__ float g_X[NTOK * ND];             //  33.5 MB  embedded tokens
__device__ float g_Hbuf[NTOK * KCAT];        // 268   MB  [t][e*NH+h] = w_e*gelu(x@W1_e)
__device__ float g_OUT[NTOK * ND];           //  33.5 MB  combined FFN output
__device__ float g_pool_part[64 * ND];
__device__ float g_pool[ND];
__device__ int   g_eidx[2];
__device__ float g_ewt[2];

// ---------------- small kernels ---------------------------------------------
__global__ void gather_kernel(const int* __restrict__ ids,
                              const float* __restrict__ emb)
{
    const int t = blockIdx.x;
    const int id = ids[t];
    const int c = threadIdx.x * 4;
    float4 v = *(const float4*)(emb + (size_t)id * ND + c);
    *(float4*)(g_X + (size_t)t * ND + c) = v;
}

__global__ void pool_partial_kernel(const int* __restrict__ ids,
                                    const float* __restrict__ emb)
{
    __shared__ int sid[128];
    const int t0 = blockIdx.x * 128;
    if (threadIdx.x < 128) sid[threadIdx.x] = ids[t0 + threadIdx.x];
    __syncthreads();
    const int c = threadIdx.x * 4;
    float4 s = make_float4(0.f, 0.f, 0.f, 0.f);
    for (int t = 0; t < 128; ++t) {
        const float4 v = *(const float4*)(emb + (size_t)sid[t] * ND + c);
        s.x += v.x; s.y += v.y; s.z += v.z; s.w += v.w;
    }
    *(float4*)(g_pool_part + blockIdx.x * ND + c) = s;
}

__global__ void pool_final_kernel()
{
    const int c = threadIdx.x * 4;
    float4 s = make_float4(0.f, 0.f, 0.f, 0.f);
    for (int b = 0; b < 64; ++b) {
        const float4 v = *(const float4*)(g_pool_part + b * ND + c);
        s.x += v.x; s.y += v.y; s.z += v.z; s.w += v.w;
    }
    const float inv = 1.0f / (float)NTOK;
    s.x *= inv; s.y *= inv; s.z *= inv; s.w *= inv;
    *(float4*)(g_pool + c) = s;
}

// 512 threads = 16 warps; warp n computes router logit n, thread 0 does top-2.
__global__ void router_kernel(const float* __restrict__ w_router)
{
    __shared__ float slog[NEXP];
    const int warp = threadIdx.x >> 5;
    const int lane = threadIdx.x & 31;
    float s = 0.f;
    for (int d = lane; d < ND; d += 32)
        s += g_pool[d] * w_router[d * NEXP + warp];
    #pragma unroll
    for (int o = 16; o > 0; o >>= 1) s += __shfl_down_sync(0xffffffffu, s, o);
    if (lane == 0) slog[warp] = s;
    __syncthreads();
    if (threadIdx.x == 0) {
        float v0 = -1e30f, v1 = -1e30f; int i0 = 0, i1 = 0;
        for (int n = 0; n < NEXP; ++n) {
            const float l = slog[n];
            if (l > v0) { v1 = v0; i1 = i0; v0 = l; i0 = n; }
            else if (l > v1) { v1 = l; i1 = n; }
        }
        // renormalized top-2 softmax weights: w0 = 1/(1+e), w1 = e/(1+e)
        const float e1  = expf(v1 - v0);
        const float den = 1.0f + e1;
        g_eidx[0] = i0; g_eidx[1] = i1;
        g_ewt[0] = 1.0f / den; g_ewt[1] = e1 / den;
    }
}

// ---------------- FFMA2 SGEMM ------------------------------------------------
#define BM 128
#define BN 128
#define BK 8

__device__ __forceinline__ unsigned long long pack2(float a)
{
    unsigned long long r;
    asm("mov.b64 %0, {%1, %1};" : "=l"(r) : "r"(__float_as_uint(a)));
    return r;
}
__device__ __forceinline__ void fma2(unsigned long long& d,
                                     unsigned long long a,
                                     unsigned long long b)
{
    asm("fma.rn.f32x2 %0, %1, %2, %0;" : "+l"(d) : "l"(a), "l"(b));
}
__device__ __forceinline__ float2 unpack2(unsigned long long v)
{
    unsigned int lo, hi;
    asm("mov.b64 {%0, %1}, %2;" : "=r"(lo), "=r"(hi) : "l"(v));
    float2 f; f.x = __uint_as_float(lo); f.y = __uint_as_float(hi);
    return f;
}
__device__ __forceinline__ float gelu_tanh(float x)
{
    const float u = 0.7978845608028654f * (x + 0.044715f * x * x * x);
    return 0.5f * x * (1.0f + tanhf(u));
}

// MODE 0: H_e = gelu(X @ W1[idx_e]) * w_e        (grid.z = expert)
// MODE 1: OUT = [H0|H1] @ [W2[idx0]; W2[idx1]]   (concatenated-K)
// MODE 2: LOGITS = OUT @ W_head
template<int MODE>
__global__ void __launch_bounds__(256, 2)
gemm_kernel(const float* __restrict__ Bsrc, float* __restrict__ Cext)
{
    constexpr int K   = (MODE == 1) ? KCAT : ND;
    constexpr int LDA = (MODE == 1) ? KCAT : ND;
    constexpr int LDB = (MODE == 0) ? NH : NV;   // unused for MODE 1
    constexpr int LDC = (MODE == 0) ? KCAT : ((MODE == 1) ? ND : NV);

    const float* A = (MODE == 0) ? g_X : ((MODE == 1) ? g_Hbuf : g_OUT);
    float*       C = (MODE == 2) ? Cext : ((MODE == 0) ? g_Hbuf : g_OUT);

    const int tid = threadIdx.x;
    const int bm  = blockIdx.y * BM;
    const int bn  = blockIdx.x * BN;

    float wt = 1.0f;
    const float* Bp = Bsrc;
    int ccol0 = bn;
    int ex0 = 0, ex1 = 0;
    if (MODE == 0) {
        const int e  = blockIdx.z;
        const int ex = g_eidx[e];
        wt    = g_ewt[e];
        Bp    = Bsrc + (size_t)ex * ND * NH;
        ccol0 = e * NH + bn;
    }
    if (MODE == 1) { ex0 = g_eidx[0]; ex1 = g_eidx[1]; }

    __shared__ __align__(16) float As[2][BK][BM];
    __shared__ __align__(16) float Bs[2][BK][BN];

    // global-load mapping
    const int arow = tid >> 1;           // 0..127
    const int acol = (tid & 1) * 4;      // 0 or 4
    const int brow = tid >> 5;           // 0..7
    const int bcol = (tid & 31) * 4;     // 0..124

    // compute mapping: 4x2 warps of 4x8 lanes, 8x8 per thread
    const int warp = tid >> 5, lane = tid & 31;
    const int m0 = (warp >> 1) * 32 + (lane & 3) * 8;
    const int n0 = (warp & 1) * 64 + (lane >> 2) * 8;

    unsigned long long acc[8][4];
    #pragma unroll
    for (int i = 0; i < 8; ++i)
        #pragma unroll
        for (int j = 0; j < 4; ++j) acc[i][j] = 0ull;

    const float* Aptr = A + (size_t)(bm + arow) * LDA + acol;

    auto loadB = [&](int kt) -> float4 {
        if (MODE == 1) {
            const int r  = kt + brow;
            const int ex = (r < NH) ? ex0 : ex1;
            const int hr = r & (NH - 1);
            return *(const float4*)(Bsrc + (size_t)ex * NH * ND +
                                    (size_t)hr * ND + bn + bcol);
        } else {
            return *(const float4*)(Bp + (size_t)(kt + brow) * LDB + bn + bcol);
        }
    };

    // prologue: tile 0 -> smem buf 0
    float4 rA = *(const float4*)(Aptr);
    float4 rB = loadB(0);
    As[0][acol + 0][arow] = rA.x;
    As[0][acol + 1][arow] = rA.y;
    As[0][acol + 2][arow] = rA.z;
    As[0][acol + 3][arow] = rA.w;
    *(float4*)&Bs[0][brow][bcol] = rB;
    __syncthreads();

    const int ktiles = K / BK;
    int buf = 0;
    for (int t = 0; t < ktiles; ++t) {
        const bool has_next = (t + 1 < ktiles);
        if (has_next) {
            rA = *(const float4*)(Aptr + (t + 1) * BK);
            rB = loadB((t + 1) * BK);
        }
        #pragma unroll
        for (int k = 0; k < BK; ++k) {
            float a[8];
            *(float4*)&a[0] = *(const float4*)&As[buf][k][m0];
            *(float4*)&a[4] = *(const float4*)&As[buf][k][m0 + 4];
            const unsigned long long* bq =
                (const unsigned long long*)&Bs[buf][k][n0];
            const unsigned long long b0 = bq[0], b1 = bq[1],
                                     b2 = bq[2], b3 = bq[3];
            #pragma unroll
            for (int i = 0; i < 8; ++i) {
                const unsigned long long ap = pack2(a[i]);
                fma2(acc[i][0], ap, b0);
                fma2(acc[i][1], ap, b1);
                fma2(acc[i][2], ap, b2);
                fma2(acc[i][3], ap, b3);
            }
        }
        if (has_next) {
            const int nb = buf ^ 1;
            As[nb][acol + 0][arow] = rA.x;
            As[nb][acol + 1][arow] = rA.y;
            As[nb][acol + 2][arow] = rA.z;
            As[nb][acol + 3][arow] = rA.w;
            *(float4*)&Bs[nb][brow][bcol] = rB;
            __syncthreads();
            buf = nb;
        }
    }

    // epilogue
    #pragma unroll
    for (int i = 0; i < 8; ++i) {
        float o[8];
        #pragma unroll
        for (int j = 0; j < 4; ++j) {
            const float2 v = unpack2(acc[i][j]);
            o[2 * j] = v.x; o[2 * j + 1] = v.y;
        }
        if (MODE == 0) {
            #pragma unroll
            for (int j = 0; j < 8; ++j) o[j] = gelu_tanh(o[j]) * wt;
        }
        float* cp = C + (size_t)(bm + m0 + i) * LDC + ccol0 + n0;
        *(float4*)(cp)     = make_float4(o[0], o[1], o[2], o[3]);
        *(float4*)(cp + 4) = make_float4(o[4], o[5], o[6], o[7]);
    }
}

// ---------------- entry point ------------------------------------------------
extern "C" void kernel_launch(void* const* d_in, const int* in_sizes, int n_in,
                              void* d_out, int out_size)
{
    (void)in_sizes; (void)n_in; (void)out_size;
    const int*   ids = (const int*)  d_in[0];  // (B,L) int32
    const float* emb = (const float*)d_in[1];  // (V,D)
    const float* wr  = (const float*)d_in[2];  // (D,N)
    const float* w1  = (const float*)d_in[3];  // (N,D,H)
    const float* w2  = (const float*)d_in[4];  // (N,H,D)
    const float* wh  = (const float*)d_in[5];  // (D,V)
    float* out = (float*)d_out;                // (B,L,V)

    gather_kernel      <<<NTOK, 256>>>(ids, emb);
    pool_partial_kernel<<<64,   256>>>(ids, emb);
    pool_final_kernel  <<<1,    256>>>();
    router_kernel      <<<1,    512>>>(wr);

    gemm_kernel<0><<<dim3(NH / BN, NTOK / BM, 2), 256>>>(w1, nullptr);
    gemm_kernel<1><<<dim3(ND / BN, NTOK / BM, 1), 256>>>(w2, nullptr);
    gemm_kernel<2><<<dim3(NV / BN, NTOK / BM, 1), 256>>>(wh, out);
}

// round 5
// speedup vs baseline: 1.7688x; 1.7688x over previous
#include <cuda_runtime.h>
#include <cuda_bf16.h>
#include <stdint.h>
#include <math.h>

// ---------------- problem dims ----------------------------------------------
#define NB   4
#define NL   2048
#define ND   1024
#define NH   4096
#define NV   32000
#define NEXP 16
#define NTOK (NB*NL)     // 8192
#define KCAT (2*NH)      // 8192

// ---------------- device scratch (no allocation allowed) --------------------
__device__ float g_X[NTOK * ND];                   //  33.5 MB
__device__ float g_Hbuf[(size_t)NTOK * KCAT];      // 268   MB
__device__ float g_OUT[NTOK * ND];                 //  33.5 MB
__device__ float g_w1t[(size_t)2 * NH * ND];       //  32   MB  [e][h][d]
__device__ float g_w2t[(size_t)ND * KCAT];         //  32   MB  [d][e*NH+h]
__device__ float g_wht[(size_t)NV * ND];           // 131   MB  [v][d]
__device__ float g_pool_part[64 * ND];
__device__ float g_pool[ND];
__device__ int   g_eidx[2];
__device__ float g_ewt[2];

// ---------------- helpers -----------------------------------------------------
__device__ __forceinline__ float gelu_tanh(float x) {
    const float u = 0.7978845608028654f * (x + 0.044715f * x * x * x);
    return 0.5f * x * (1.0f + tanhf(u));
}

// pack two bf16 (a = lower/even k, b = upper/odd k)
__device__ __forceinline__ uint32_t pkbf(__nv_bfloat16 a, __nv_bfloat16 b) {
    return (uint32_t)__bfloat16_as_ushort(a) |
           ((uint32_t)__bfloat16_as_ushort(b) << 16);
}

__device__ __forceinline__ void mma_bf16(float* d, const uint32_t* a,
                                         const uint32_t* b) {
    asm volatile(
        "mma.sync.aligned.m16n8k16.row.col.f32.bf16.bf16.f32 "
        "{%0,%1,%2,%3}, {%4,%5,%6,%7}, {%8,%9}, {%0,%1,%2,%3};"
        : "+f"(d[0]), "+f"(d[1]), "+f"(d[2]), "+f"(d[3])
        : "r"(a[0]), "r"(a[1]), "r"(a[2]), "r"(a[3]),
          "r"(b[0]), "r"(b[1]));
}

// ---------------- embed / pool / router --------------------------------------
__global__ void gather_kernel(const int* __restrict__ ids,
                              const float* __restrict__ emb)
{
    const int t = blockIdx.x;
    const int id = ids[t];
    const int c = threadIdx.x * 4;
    float4 v = *(const float4*)(emb + (size_t)id * ND + c);
    *(float4*)(g_X + (size_t)t * ND + c) = v;
}

__global__ void pool_partial_kernel(const int* __restrict__ ids,
                                    const float* __restrict__ emb)
{
    __shared__ int sid[128];
    const int t0 = blockIdx.x * 128;
    if (threadIdx.x < 128) sid[threadIdx.x] = ids[t0 + threadIdx.x];
    __syncthreads();
    const int c = threadIdx.x * 4;
    float4 s = make_float4(0.f, 0.f, 0.f, 0.f);
    for (int t = 0; t < 128; ++t) {
        const float4 v = *(const float4*)(emb + (size_t)sid[t] * ND + c);
        s.x += v.x; s.y += v.y; s.z += v.z; s.w += v.w;
    }
    *(float4*)(g_pool_part + blockIdx.x * ND + c) = s;
}

__global__ void pool_final_kernel()
{
    const int c = threadIdx.x * 4;
    float4 s = make_float4(0.f, 0.f, 0.f, 0.f);
    for (int b = 0; b < 64; ++b) {
        const float4 v = *(const float4*)(g_pool_part + b * ND + c);
        s.x += v.x; s.y += v.y; s.z += v.z; s.w += v.w;
    }
    const float inv = 1.0f / (float)NTOK;
    s.x *= inv; s.y *= inv; s.z *= inv; s.w *= inv;
    *(float4*)(g_pool + c) = s;
}

__global__ void router_kernel(const float* __restrict__ w_router)
{
    __shared__ float slog[NEXP];
    const int warp = threadIdx.x >> 5;
    const int lane = threadIdx.x & 31;
    float s = 0.f;
    for (int d = lane; d < ND; d += 32)
        s += g_pool[d] * w_router[d * NEXP + warp];
    #pragma unroll
    for (int o = 16; o > 0; o >>= 1) s += __shfl_down_sync(0xffffffffu, s, o);
    if (lane == 0) slog[warp] = s;
    __syncthreads();
    if (threadIdx.x == 0) {
        float v0 = -1e30f, v1 = -1e30f; int i0 = 0, i1 = 0;
        for (int n = 0; n < NEXP; ++n) {
            const float l = slog[n];
            if (l > v0) { v1 = v0; i1 = i0; v0 = l; i0 = n; }
            else if (l > v1) { v1 = l; i1 = n; }
        }
        const float e1  = expf(v1 - v0);
        const float den = 1.0f + e1;
        g_eidx[0] = i0; g_eidx[1] = i1;
        g_ewt[0] = 1.0f / den; g_ewt[1] = e1 / den;
    }
}

// ---------------- weight transpose -------------------------------------------
__global__ void transpose_kernel(const float* __restrict__ src,
                                 int K, int N, long src_z, int mode)
{
    __shared__ float tile[32][33];
    const int e = blockIdx.z;
    float* dst; long dst_z; int ld; int use_e;
    if (mode == 0)      { dst = g_w1t; dst_z = (long)NH * ND; ld = ND;   use_e = 1; }
    else if (mode == 1) { dst = g_w2t; dst_z = NH;            ld = KCAT; use_e = 1; }
    else                { dst = g_wht; dst_z = 0;             ld = ND;   use_e = 0; }

    const int sel = use_e ? g_eidx[e] : e;
    const float* in = src + (size_t)sel * src_z;
    float* out = dst + (size_t)e * dst_z;

    const int n0 = blockIdx.x * 32, k0 = blockIdx.y * 32;
    const int tx = threadIdx.x, ty = threadIdx.y;   // (32, 8)
    #pragma unroll
    for (int j = 0; j < 32; j += 8)
        tile[ty + j][tx] = in[(size_t)(k0 + ty + j) * N + n0 + tx];
    __syncthreads();
    #pragma unroll
    for (int j = 0; j < 32; j += 8)
        out[(size_t)(n0 + ty + j) * ld + k0 + tx] = tile[tx][ty + j];
}

// ---------------- bf16-split mma.sync GEMM ------------------------------------
// C = A(fp32)[M,K] @ B(fp32)[N,K]^T with 2-term bf16 split (HH+HL+LH), fp32 acc.
#define BM 128
#define BN 256
#define BK 16

// smem word-layout per buffer (uint32 units):
//  AH [8][136], AL [8][136], BH [8][264], BL [8][264]
#define SA_STR 136
#define SB_STR 264
#define OFF_AL 1088
#define OFF_BH 2176
#define OFF_BL 4288
#define BUF_WORDS 6400
#define SMEM_BYTES (2 * BUF_WORDS * 4)   // 51200

// MODE 0: Hbuf[:, e*NH+..] = gelu(X @ w1t[e]^T) * wt[e]   (grid.z = expert)
// MODE 1: OUT = Hbuf @ w2t^T
// MODE 2: LOGITS = OUT @ wht^T
template<int MODE>
__global__ void __launch_bounds__(256, 1)
mma_gemm_kernel(float* __restrict__ Cext)
{
    constexpr int K   = (MODE == 1) ? KCAT : ND;
    constexpr int LDC = (MODE == 0) ? KCAT : ((MODE == 1) ? ND : NV);
    constexpr int NT  = K / BK;

    const float* A  = (MODE == 0) ? g_X   : ((MODE == 1) ? g_Hbuf : g_OUT);
    const float* Bt = (MODE == 0) ? g_w1t : ((MODE == 1) ? g_w2t  : g_wht);
    float*       C  = (MODE == 2) ? Cext  : ((MODE == 0) ? g_Hbuf : g_OUT);

    extern __shared__ uint32_t sm[];

    const int tid  = threadIdx.x;
    const int w    = tid >> 5, lane = tid & 31;
    const int g    = lane >> 2, tig = lane & 3;
    const int mb   = (w >> 2) * 64;        // warp m offset in block tile
    const int nb   = (w & 3) * 64;         // warp n offset
    const int bm   = blockIdx.y * BM;
    const int bn   = blockIdx.x * BN;

    float wt = 1.f; int ccol0 = bn;
    const float* Bp = Bt;
    if (MODE == 0) {
        const int e = blockIdx.z;
        wt    = g_ewt[e];
        Bp    = Bt + (size_t)e * NH * ND;
        ccol0 = e * NH + bn;
    }

    const float* Ab0 = A  + (size_t)bm * K;
    const float* Bb0 = Bp + (size_t)bn * K;

    float acc[4][8][4];
    #pragma unroll
    for (int i = 0; i < 4; ++i)
        #pragma unroll
        for (int j = 0; j < 8; ++j)
            #pragma unroll
            for (int q = 0; q < 4; ++q) acc[i][j][q] = 0.f;

    // ---- fill helpers (register staging -> convert -> STS) ----
    float4 ra[2], rb[4];

    auto load_regs = [&](int k0) {
        #pragma unroll
        for (int i = 0; i < 2; ++i) {
            const int idx = i * 256 + tid;
            const int r = idx >> 2, t4 = (idx & 3) * 4;
            ra[i] = *(const float4*)(Ab0 + (size_t)r * K + k0 + t4);
        }
        #pragma unroll
        for (int i = 0; i < 4; ++i) {
            const int idx = i * 256 + tid;
            const int r = idx >> 2, t4 = (idx & 3) * 4;
            rb[i] = *(const float4*)(Bb0 + (size_t)r * K + k0 + t4);
        }
    };

    auto cvt_sts = [&](uint32_t* dh, uint32_t* dl, int stride, int r, int t,
                       float4 v) {
        __nv_bfloat16 h0 = __float2bfloat16(v.x);
        __nv_bfloat16 h1 = __float2bfloat16(v.y);
        __nv_bfloat16 h2 = __float2bfloat16(v.z);
        __nv_bfloat16 h3 = __float2bfloat16(v.w);
        __nv_bfloat16 l0 = __float2bfloat16(v.x - __bfloat162float(h0));
        __nv_bfloat16 l1 = __float2bfloat16(v.y - __bfloat162float(h1));
        __nv_bfloat16 l2 = __float2bfloat16(v.z - __bfloat162float(h2));
        __nv_bfloat16 l3 = __float2bfloat16(v.w - __bfloat162float(h3));
        dh[(2 * t)     * stride + r] = pkbf(h0, h1);
        dh[(2 * t + 1) * stride + r] = pkbf(h2, h3);
        dl[(2 * t)     * stride + r] = pkbf(l0, l1);
        dl[(2 * t + 1) * stride + r] = pkbf(l2, l3);
    };

    auto store_smem = [&](int buf) {
        uint32_t* S = sm + buf * BUF_WORDS;
        #pragma unroll
        for (int i = 0; i < 2; ++i) {
            const int idx = i * 256 + tid;
            cvt_sts(S, S + OFF_AL, SA_STR, idx >> 2, idx & 3, ra[i]);
        }
        #pragma unroll
        for (int i = 0; i < 4; ++i) {
            const int idx = i * 256 + tid;
            cvt_sts(S + OFF_BH, S + OFF_BL, SB_STR, idx >> 2, idx & 3, rb[i]);
        }
    };

    // prologue
    load_regs(0);
    store_smem(0);
    __syncthreads();

    #pragma unroll 1
    for (int t = 0; t < NT; ++t) {
        if (t + 1 < NT) load_regs((t + 1) * BK);

        const uint32_t* S = sm + (t & 1) * BUF_WORDS;

        // B fragments for all 8 n-tiles (hi + lo)
        uint32_t Bh[8][2], Bl[8][2];
        #pragma unroll
        for (int nt = 0; nt < 8; ++nt) {
            const int c = nb + nt * 8 + g;
            Bh[nt][0] = S[OFF_BH + tig * SB_STR + c];
            Bh[nt][1] = S[OFF_BH + (tig + 4) * SB_STR + c];
            Bl[nt][0] = S[OFF_BL + tig * SB_STR + c];
            Bl[nt][1] = S[OFF_BL + (tig + 4) * SB_STR + c];
        }
        #pragma unroll
        for (int mt = 0; mt < 4; ++mt) {
            const int r = mb + mt * 16 + g;
            uint32_t Ah[4], Al[4];
            Ah[0] = S[tig * SA_STR + r];
            Ah[1] = S[tig * SA_STR + r + 8];
            Ah[2] = S[(tig + 4) * SA_STR + r];
            Ah[3] = S[(tig + 4) * SA_STR + r + 8];
            Al[0] = S[OFF_AL + tig * SA_STR + r];
            Al[1] = S[OFF_AL + tig * SA_STR + r + 8];
            Al[2] = S[OFF_AL + (tig + 4) * SA_STR + r];
            Al[3] = S[OFF_AL + (tig + 4) * SA_STR + r + 8];
            #pragma unroll
            for (int nt = 0; nt < 8; ++nt) {
                mma_bf16(acc[mt][nt], Ah, Bh[nt]);
                mma_bf16(acc[mt][nt], Ah, Bl[nt]);
                mma_bf16(acc[mt][nt], Al, Bh[nt]);
            }
        }

        if (t + 1 < NT) {
            __syncthreads();          // everyone done reading buf (t+1)&1
            store_smem((t + 1) & 1);
            __syncthreads();
        }
    }

    // ---- epilogue ----
    #pragma unroll
    for (int mt = 0; mt < 4; ++mt) {
        const int row0 = bm + mb + mt * 16 + g;
        #pragma unroll
        for (int rr = 0; rr < 2; ++rr) {
            float* cp = C + (size_t)(row0 + rr * 8) * LDC + ccol0 + nb + 2 * tig;
            #pragma unroll
            for (int nt = 0; nt < 8; ++nt) {
                float v0 = acc[mt][nt][2 * rr];
                float v1 = acc[mt][nt][2 * rr + 1];
                if (MODE == 0) {
                    v0 = gelu_tanh(v0) * wt;
                    v1 = gelu_tanh(v1) * wt;
                }
                *(float2*)(cp + nt * 8) = make_float2(v0, v1);
            }
        }
    }
}

// ---------------- entry point -------------------------------------------------
extern "C" void kernel_launch(void* const* d_in, const int* in_sizes, int n_in,
                              void* d_out, int out_size)
{
    (void)in_sizes; (void)n_in; (void)out_size;
    const int*   ids = (const int*)  d_in[0];
    const float* emb = (const float*)d_in[1];
    const float* wr  = (const float*)d_in[2];
    const float* w1  = (const float*)d_in[3];
    const float* w2  = (const float*)d_in[4];
    const float* wh  = (const float*)d_in[5];
    float* out = (float*)d_out;

    cudaFuncSetAttribute(mma_gemm_kernel<0>, cudaFuncAttributeMaxDynamicSharedMemorySize, SMEM_BYTES);
    cudaFuncSetAttribute(mma_gemm_kernel<1>, cudaFuncAttributeMaxDynamicSharedMemorySize, SMEM_BYTES);
    cudaFuncSetAttribute(mma_gemm_kernel<2>, cudaFuncAttributeMaxDynamicSharedMemorySize, SMEM_BYTES);

    gather_kernel      <<<NTOK, 256>>>(ids, emb);
    pool_partial_kernel<<<64,   256>>>(ids, emb);
    pool_final_kernel  <<<1,    256>>>();
    router_kernel      <<<1,    512>>>(wr);

    transpose_kernel<<<dim3(NH / 32, ND / 32, 2), dim3(32, 8)>>>(w1, ND, NH, (long)ND * NH, 0);
    transpose_kernel<<<dim3(ND / 32, NH / 32, 2), dim3(32, 8)>>>(w2, NH, ND, (long)NH * ND, 1);
    transpose_kernel<<<dim3(NV / 32, ND / 32, 1), dim3(32, 8)>>>(wh, ND, NV, 0, 2);

    mma_gemm_kernel<0><<<dim3(NH / BN, NTOK / BM, 2), 256, SMEM_BYTES>>>(nullptr);
    mma_gemm_kernel<1><<<dim3(ND / BN, NTOK / BM, 1), 256, SMEM_BYTES>>>(nullptr);
    mma_gemm_kernel<2><<<dim3(NV / BN, NTOK / BM, 1), 256, SMEM_BYTES>>>(out);
}

// round 6
// speedup vs baseline: 2.0407x; 1.1537x over previous
#include <cuda_runtime.h>
#include <cuda_bf16.h>
#include <stdint.h>
#include <math.h>

// ---------------- problem dims ----------------------------------------------
#define NB   4
#define NL   2048
#define ND   1024
#define NH   4096
#define NV   32000
#define NEXP 16
#define NTOK (NB*NL)     // 8192
#define KCAT (2*NH)      // 8192

// ---------------- persistent bf16 hi/lo operand storage ----------------------
__device__ __nv_bfloat16 g_Xh[NTOK * ND],  g_Xl[NTOK * ND];
__device__ __nv_bfloat16 g_Hh[(size_t)NTOK * KCAT], g_Hl[(size_t)NTOK * KCAT];
__device__ __nv_bfloat16 g_Oh[NTOK * ND],  g_Ol[NTOK * ND];
__device__ __nv_bfloat16 g_w1h[(size_t)2 * NH * ND], g_w1l[(size_t)2 * NH * ND];
__device__ __nv_bfloat16 g_w2h[(size_t)ND * KCAT],   g_w2l[(size_t)ND * KCAT];
__device__ __nv_bfloat16 g_whh[(size_t)NV * ND],     g_whl[(size_t)NV * ND];
__device__ float g_pool_part[64 * ND];
__device__ float g_pool[ND];
__device__ int   g_eidx[2];
__device__ float g_ewt[2];

// ---------------- helpers -----------------------------------------------------
__device__ __forceinline__ float gelu_tanh(float x) {
    const float u = 0.7978845608028654f * (x + 0.044715f * x * x * x);
    return 0.5f * x * (1.0f + tanhf(u));
}
__device__ __forceinline__ uint32_t pkbf(__nv_bfloat16 a, __nv_bfloat16 b) {
    return (uint32_t)__bfloat16_as_ushort(a) |
           ((uint32_t)__bfloat16_as_ushort(b) << 16);
}
__device__ __forceinline__ void split2(float v, __nv_bfloat16& h, __nv_bfloat16& l) {
    h = __float2bfloat16(v);
    l = __float2bfloat16(v - __bfloat162float(h));
}
__device__ __forceinline__ uint32_t s2u(const void* p) {
    uint32_t a;
    asm("{ .reg .u64 t; cvta.to.shared.u64 t, %1; cvt.u32.u64 %0, t; }"
        : "=r"(a) : "l"(p));
    return a;
}

__device__ __forceinline__ void mma_bf16(float* d, const uint32_t* a,
                                         const uint32_t* b) {
    asm volatile(
        "mma.sync.aligned.m16n8k16.row.col.f32.bf16.bf16.f32 "
        "{%0,%1,%2,%3}, {%4,%5,%6,%7}, {%8,%9}, {%0,%1,%2,%3};"
        : "+f"(d[0]), "+f"(d[1]), "+f"(d[2]), "+f"(d[3])
        : "r"(a[0]), "r"(a[1]), "r"(a[2]), "r"(a[3]),
          "r"(b[0]), "r"(b[1]));
}

#define LDSM4(r0, r1, r2, r3, addr) \
    asm volatile("ldmatrix.sync.aligned.m8n8.x4.shared.b16 {%0,%1,%2,%3}, [%4];" \
        : "=r"(r0), "=r"(r1), "=r"(r2), "=r"(r3) : "r"(addr))

#define CPASYNC16(dst, src) \
    asm volatile("cp.async.cg.shared.global [%0], [%1], 16;" \
        :: "r"(dst), "l"(src) : "memory")
#define CPCOMMIT() asm volatile("cp.async.commit_group;" ::: "memory")
#define CPWAIT1()  asm volatile("cp.async.wait_group 1;"  ::: "memory")

// chunk swizzle: 16B chunks, ci ^ bit3->bit0 (keeps ldmatrix 8-row phases conflict-free)
#define SWZ16(ci) ((uint32_t)(((ci) ^ (((ci) >> 3) & 1)) * 16))

// ---------------- embed / pool / router --------------------------------------
__global__ void gather_split_kernel(const int* __restrict__ ids,
                                    const float* __restrict__ emb)
{
    const int t = blockIdx.x;
    const int id = ids[t];
    const int c = threadIdx.x * 4;
    float4 v = *(const float4*)(emb + (size_t)id * ND + c);
    __nv_bfloat16 h0, h1, h2, h3, l0, l1, l2, l3;
    split2(v.x, h0, l0); split2(v.y, h1, l1);
    split2(v.z, h2, l2); split2(v.w, h3, l3);
    *(uint2*)(g_Xh + (size_t)t * ND + c) = make_uint2(pkbf(h0, h1), pkbf(h2, h3));
    *(uint2*)(g_Xl + (size_t)t * ND + c) = make_uint2(pkbf(l0, l1), pkbf(l2, l3));
}

__global__ void pool_partial_kernel(const int* __restrict__ ids,
                                    const float* __restrict__ emb)
{
    __shared__ int sid[128];
    const int t0 = blockIdx.x * 128;
    if (threadIdx.x < 128) sid[threadIdx.x] = ids[t0 + threadIdx.x];
    __syncthreads();
    const int c = threadIdx.x * 4;
    float4 s = make_float4(0.f, 0.f, 0.f, 0.f);
    for (int t = 0; t < 128; ++t) {
        const float4 v = *(const float4*)(emb + (size_t)sid[t] * ND + c);
        s.x += v.x; s.y += v.y; s.z += v.z; s.w += v.w;
    }
    *(float4*)(g_pool_part + blockIdx.x * ND + c) = s;
}

__global__ void pool_final_kernel()
{
    const int c = threadIdx.x * 4;
    float4 s = make_float4(0.f, 0.f, 0.f, 0.f);
    for (int b = 0; b < 64; ++b) {
        const float4 v = *(const float4*)(g_pool_part + b * ND + c);
        s.x += v.x; s.y += v.y; s.z += v.z; s.w += v.w;
    }
    const float inv = 1.0f / (float)NTOK;
    s.x *= inv; s.y *= inv; s.z *= inv; s.w *= inv;
    *(float4*)(g_pool + c) = s;
}

__global__ void router_kernel(const float* __restrict__ w_router)
{
    __shared__ float slog[NEXP];
    const int warp = threadIdx.x >> 5;
    const int lane = threadIdx.x & 31;
    float s = 0.f;
    for (int d = lane; d < ND; d += 32)
        s += g_pool[d] * w_router[d * NEXP + warp];
    #pragma unroll
    for (int o = 16; o > 0; o >>= 1) s += __shfl_down_sync(0xffffffffu, s, o);
    if (lane == 0) slog[warp] = s;
    __syncthreads();
    if (threadIdx.x == 0) {
        float v0 = -1e30f, v1 = -1e30f; int i0 = 0, i1 = 0;
        for (int n = 0; n < NEXP; ++n) {
            const float l = slog[n];
            if (l > v0) { v1 = v0; i1 = i0; v0 = l; i0 = n; }
            else if (l > v1) { v1 = l; i1 = n; }
        }
        const float e1  = expf(v1 - v0);
        const float den = 1.0f + e1;
        g_eidx[0] = i0; g_eidx[1] = i1;
        g_ewt[0] = 1.0f / den; g_ewt[1] = e1 / den;
    }
}

// ---------------- weight transpose + split ------------------------------------
// mode 0: w1[eidx[e]] (D,H) -> g_w1h/l + e*NH*ND  [h][d]
// mode 1: w2[eidx[e]] (H,D) -> g_w2h/l cols e*NH  [d][e*NH+h], ld=KCAT
// mode 2: w_head      (D,V) -> g_whh/l            [v][d]
__global__ void transpose_split_kernel(const float* __restrict__ src,
                                       int K, int N, long src_z, int mode)
{
    __shared__ float tile[32][33];
    const int e = blockIdx.z;
    __nv_bfloat16 *dh, *dl; long dst_z; int ld; int use_e;
    if (mode == 0)      { dh = g_w1h; dl = g_w1l; dst_z = (long)NH * ND; ld = ND;   use_e = 1; }
    else if (mode == 1) { dh = g_w2h; dl = g_w2l; dst_z = NH;            ld = KCAT; use_e = 1; }
    else                { dh = g_whh; dl = g_whl; dst_z = 0;             ld = ND;   use_e = 0; }

    const int sel = use_e ? g_eidx[e] : e;
    const float* in = src + (size_t)sel * src_z;
    dh += (size_t)e * dst_z;
    dl += (size_t)e * dst_z;

    const int n0 = blockIdx.x * 32, k0 = blockIdx.y * 32;
    const int tx = threadIdx.x, ty = threadIdx.y;   // (32, 8)
    #pragma unroll
    for (int j = 0; j < 32; j += 8)
        tile[ty + j][tx] = in[(size_t)(k0 + ty + j) * N + n0 + tx];
    __syncthreads();
    #pragma unroll
    for (int j = 0; j < 32; j += 8) {
        const float v = tile[tx][ty + j];
        __nv_bfloat16 h, l; split2(v, h, l);
        const size_t o = (size_t)(n0 + ty + j) * ld + k0 + tx;
        dh[o] = h; dl[o] = l;
    }
}

// ---------------- bf16-split mma.sync GEMM, cp.async 3-stage -------------------
#define BM 128
#define BN 256
#define BK 16
#define NSTAGE 3
// per-stage byte layout: AH[128 rows x 32B] AL BH[256 x 32B] BL
#define OFF_AL 4096
#define OFF_BH 8192
#define OFF_BL 16384
#define STAGE  24576
#define SMEM_BYTES (NSTAGE * STAGE)   // 73728

// MODE 0: H = gelu(X @ w1t[e]^T)*wt[e] -> Hh/Hl   (grid.z = expert)
// MODE 1: O = H @ w2t^T -> Oh/Ol
// MODE 2: LOGITS = O @ wht^T -> fp32 out
template<int MODE>
__global__ void __launch_bounds__(256, 1)
mma_gemm_kernel(float* __restrict__ Cext)
{
    constexpr int K   = (MODE == 1) ? KCAT : ND;
    constexpr int NT  = K / BK;
    constexpr int LDC = (MODE == 0) ? KCAT : ((MODE == 1) ? ND : NV);

    const __nv_bfloat16 *Ah, *Al, *Bh_, *Bl_;
    if (MODE == 0)      { Ah = g_Xh; Al = g_Xl; Bh_ = g_w1h; Bl_ = g_w1l; }
    else if (MODE == 1) { Ah = g_Hh; Al = g_Hl; Bh_ = g_w2h; Bl_ = g_w2l; }
    else                { Ah = g_Oh; Al = g_Ol; Bh_ = g_whh; Bl_ = g_whl; }

    extern __shared__ __align__(16) uint8_t smraw[];
    const uint32_t smb = s2u(smraw);

    const int tid  = threadIdx.x;
    const int w    = tid >> 5, lane = tid & 31;
    const int g    = lane >> 2, tig = lane & 3;
    const int mb   = (w >> 2) * 64;
    const int nb   = (w & 3) * 64;
    const int bm   = blockIdx.y * BM;
    const int bn   = blockIdx.x * BN;

    float wt = 1.f; int ccol0 = bn;
    if (MODE == 0) {
        const int e = blockIdx.z;
        wt    = g_ewt[e];
        Bh_  += (size_t)e * NH * ND;
        Bl_  += (size_t)e * NH * ND;
        ccol0 = e * NH + bn;
    }

    const __nv_bfloat16* Ab_h = Ah + (size_t)bm * K;
    const __nv_bfloat16* Ab_l = Al + (size_t)bm * K;
    const __nv_bfloat16* Bb_h = Bh_ + (size_t)bn * K;
    const __nv_bfloat16* Bb_l = Bl_ + (size_t)bn * K;

    // fill: 1536 16B chunks / 256 threads = 6 each (regions compile-time per i)
    auto fill = [&](uint32_t sbase, int k0) {
        {   // AH: ci = tid (128 rows x 2 chunks)
            const int ci = tid;
            CPASYNC16(sbase + SWZ16(ci),
                      Ab_h + (size_t)(ci >> 1) * K + k0 + (ci & 1) * 8);
        }
        {   // AL
            const int ci = tid;
            CPASYNC16(sbase + OFF_AL + SWZ16(ci),
                      Ab_l + (size_t)(ci >> 1) * K + k0 + (ci & 1) * 8);
        }
        #pragma unroll
        for (int i = 0; i < 2; ++i) {   // BH: ci = tid, 256+tid
            const int ci = i * 256 + tid;
            CPASYNC16(sbase + OFF_BH + SWZ16(ci),
                      Bb_h + (size_t)(ci >> 1) * K + k0 + (ci & 1) * 8);
        }
        #pragma unroll
        for (int i = 0; i < 2; ++i) {   // BL
            const int ci = i * 256 + tid;
            CPASYNC16(sbase + OFF_BL + SWZ16(ci),
                      Bb_l + (size_t)(ci >> 1) * K + k0 + (ci & 1) * 8);
        }
    };

    // precomputed ldmatrix lane offsets (within region, stage-relative)
    const int am = lane >> 3;
    const int a_ci0 = (mb + ((am & 1) << 3) + (lane & 7)) * 2 + (am >> 1);
    const uint32_t aoff = SWZ16(a_ci0);
    const int bmm = lane >> 3;
    const int b_ci0 = (nb + ((bmm >> 1) << 3) + (lane & 7)) * 2 + (bmm & 1);
    const uint32_t boff = SWZ16(b_ci0);

    float acc[4][8][4];
    #pragma unroll
    for (int i = 0; i < 4; ++i)
        #pragma unroll
        for (int j = 0; j < 8; ++j)
            #pragma unroll
            for (int q = 0; q < 4; ++q) acc[i][j][q] = 0.f;

    // prologue: stages 0,1 in flight
    fill(smb, 0);            CPCOMMIT();
    fill(smb + STAGE, BK);   CPCOMMIT();

    int rd = 0, wr = 2;
    #pragma unroll 1
    for (int t = 0; t < NT; ++t) {
        CPWAIT1();
        __syncthreads();

        if (t + 2 < NT) fill(smb + wr * STAGE, (t + 2) * BK);
        CPCOMMIT();

        const uint32_t sb = smb + rd * STAGE;

        uint32_t Bhf[8][2], Blf[8][2];
        #pragma unroll
        for (int p = 0; p < 4; ++p) {
            uint32_t r0, r1, r2, r3;
            LDSM4(r0, r1, r2, r3, sb + OFF_BH + boff + p * 512);
            Bhf[2*p][0] = r0; Bhf[2*p][1] = r1;
            Bhf[2*p+1][0] = r2; Bhf[2*p+1][1] = r3;
            LDSM4(r0, r1, r2, r3, sb + OFF_BL + boff + p * 512);
            Blf[2*p][0] = r0; Blf[2*p][1] = r1;
            Blf[2*p+1][0] = r2; Blf[2*p+1][1] = r3;
        }
        #pragma unroll
        for (int mt = 0; mt < 4; ++mt) {
            uint32_t Ahf[4], Alf[4];
            LDSM4(Ahf[0], Ahf[1], Ahf[2], Ahf[3], sb + aoff + mt * 512);
            LDSM4(Alf[0], Alf[1], Alf[2], Alf[3], sb + OFF_AL + aoff + mt * 512);
            #pragma unroll
            for (int nt = 0; nt < 8; ++nt) {
                mma_bf16(acc[mt][nt], Ahf, Bhf[nt]);
                mma_bf16(acc[mt][nt], Ahf, Blf[nt]);
                mma_bf16(acc[mt][nt], Alf, Bhf[nt]);
            }
        }

        rd = (rd == NSTAGE - 1) ? 0 : rd + 1;
        wr = (wr == NSTAGE - 1) ? 0 : wr + 1;
    }

    // ---- epilogue ----
    #pragma unroll
    for (int mt = 0; mt < 4; ++mt) {
        const int row0 = bm + mb + mt * 16 + g;
        #pragma unroll
        for (int rr = 0; rr < 2; ++rr) {
            const int row = row0 + rr * 8;
            const size_t base = (size_t)row * LDC + ccol0 + nb + 2 * tig;
            #pragma unroll
            for (int nt = 0; nt < 8; ++nt) {
                float v0 = acc[mt][nt][2 * rr];
                float v1 = acc[mt][nt][2 * rr + 1];
                if (MODE == 0) {
                    v0 = gelu_tanh(v0) * wt;
                    v1 = gelu_tanh(v1) * wt;
                }
                if (MODE == 2) {
                    *(float2*)(Cext + base + nt * 8) = make_float2(v0, v1);
                } else {
                    __nv_bfloat16 h0, l0, h1, l1;
                    split2(v0, h0, l0); split2(v1, h1, l1);
                    __nv_bfloat16* dh = (MODE == 0) ? g_Hh : g_Oh;
                    __nv_bfloat16* dl = (MODE == 0) ? g_Hl : g_Ol;
                    *(uint32_t*)(dh + base + nt * 8) = pkbf(h0, h1);
                    *(uint32_t*)(dl + base + nt * 8) = pkbf(l0, l1);
                }
            }
        }
    }
}

// ---------------- entry point -------------------------------------------------
extern "C" void kernel_launch(void* const* d_in, const int* in_sizes, int n_in,
                              void* d_out, int out_size)
{
    (void)in_sizes; (void)n_in; (void)out_size;
    const int*   ids = (const int*)  d_in[0];
    const float* emb = (const float*)d_in[1];
    const float* wr  = (const float*)d_in[2];
    const float* w1  = (const float*)d_in[3];
    const float* w2  = (const float*)d_in[4];
    const float* wh  = (const float*)d_in[5];
    float* out = (float*)d_out;

    cudaFuncSetAttribute(mma_gemm_kernel<0>, cudaFuncAttributeMaxDynamicSharedMemorySize, SMEM_BYTES);
    cudaFuncSetAttribute(mma_gemm_kernel<1>, cudaFuncAttributeMaxDynamicSharedMemorySize, SMEM_BYTES);
    cudaFuncSetAttribute(mma_gemm_kernel<2>, cudaFuncAttributeMaxDynamicSharedMemorySize, SMEM_BYTES);

    gather_split_kernel<<<NTOK, 256>>>(ids, emb);
    pool_partial_kernel<<<64,   256>>>(ids, emb);
    pool_final_kernel  <<<1,    256>>>();
    router_kernel      <<<1,    512>>>(wr);

    transpose_split_kernel<<<dim3(NH / 32, ND / 32, 2), dim3(32, 8)>>>(w1, ND, NH, (long)ND * NH, 0);
    transpose_split_kernel<<<dim3(ND / 32, NH / 32, 2), dim3(32, 8)>>>(w2, NH, ND, (long)NH * ND, 1);
    transpose_split_kernel<<<dim3(NV / 32, ND / 32, 1), dim3(32, 8)>>>(wh, ND, NV, 0, 2);

    mma_gemm_kernel<0><<<dim3(NH / BN, NTOK / BM, 2), 256, SMEM_BYTES>>>(nullptr);
    mma_gemm_kernel<1><<<dim3(ND / BN, NTOK / BM, 1), 256, SMEM_BYTES>>>(nullptr);
    mma_gemm_kernel<2><<<dim3(NV / BN, NTOK / BM, 1), 256, SMEM_BYTES>>>(out);
}

// round 7
// speedup vs baseline: 2.3047x; 1.1294x over previous
#include <cuda_runtime.h>
#include <cuda_bf16.h>
#include <stdint.h>
#include <math.h>

// ---------------- problem dims ----------------------------------------------
#define NB   4
#define NL   2048
#define ND   1024
#define NH   4096
#define NV   32000
#define NEXP 16
#define NTOK (NB*NL)     // 8192
#define KCAT (2*NH)      // 8192

// ---------------- persistent bf16 hi/lo operand storage ----------------------
__device__ __nv_bfloat16 g_Xh[NTOK * ND],  g_Xl[NTOK * ND];
__device__ __nv_bfloat16 g_Hh[(size_t)NTOK * KCAT], g_Hl[(size_t)NTOK * KCAT];
__device__ __nv_bfloat16 g_Oh[NTOK * ND],  g_Ol[NTOK * ND];
__device__ __nv_bfloat16 g_w1h[(size_t)2 * NH * ND], g_w1l[(size_t)2 * NH * ND];
__device__ __nv_bfloat16 g_w2h[(size_t)ND * KCAT],   g_w2l[(size_t)ND * KCAT];
__device__ __nv_bfloat16 g_whh[(size_t)NV * ND],     g_whl[(size_t)NV * ND];
__device__ float g_pool_part[64 * ND];
__device__ float g_pool[ND];
__device__ int   g_eidx[2];
__device__ float g_ewt[2];

// ---------------- helpers -----------------------------------------------------
__device__ __forceinline__ float gelu_tanh(float x) {
    const float u = 0.7978845608028654f * (x + 0.044715f * x * x * x);
    return 0.5f * x * (1.0f + tanhf(u));
}
__device__ __forceinline__ uint32_t pkbf(__nv_bfloat16 a, __nv_bfloat16 b) {
    return (uint32_t)__bfloat16_as_ushort(a) |
           ((uint32_t)__bfloat16_as_ushort(b) << 16);
}
__device__ __forceinline__ void split2(float v, __nv_bfloat16& h, __nv_bfloat16& l) {
    h = __float2bfloat16(v);
    l = __float2bfloat16(v - __bfloat162float(h));
}
__device__ __forceinline__ uint32_t s2u(const void* p) {
    uint32_t a;
    asm("{ .reg .u64 t; cvta.to.shared.u64 t, %1; cvt.u32.u64 %0, t; }"
        : "=r"(a) : "l"(p));
    return a;
}

__device__ __forceinline__ void mma_bf16(float* d, const uint32_t* a,
                                         const uint32_t* b) {
    asm volatile(
        "mma.sync.aligned.m16n8k16.row.col.f32.bf16.bf16.f32 "
        "{%0,%1,%2,%3}, {%4,%5,%6,%7}, {%8,%9}, {%0,%1,%2,%3};"
        : "+f"(d[0]), "+f"(d[1]), "+f"(d[2]), "+f"(d[3])
        : "r"(a[0]), "r"(a[1]), "r"(a[2]), "r"(a[3]),
          "r"(b[0]), "r"(b[1]));
}

#define LDSM4(r0, r1, r2, r3, addr) \
    asm volatile("ldmatrix.sync.aligned.m8n8.x4.shared.b16 {%0,%1,%2,%3}, [%4];" \
        : "=r"(r0), "=r"(r1), "=r"(r2), "=r"(r3) : "r"(addr))

#define CPASYNC16(dst, src) \
    asm volatile("cp.async.cg.shared.global [%0], [%1], 16;" \
        :: "r"(dst), "l"(src) : "memory")
#define CPCOMMIT() asm volatile("cp.async.commit_group;" ::: "memory")
#define CPWAIT2()  asm volatile("cp.async.wait_group 2;"  ::: "memory")

// chunk swizzle: 16B chunks, ci ^ bit3->bit0 (keeps ldmatrix 8-row phases conflict-free)
#define SWZ16(ci) ((uint32_t)(((ci) ^ (((ci) >> 3) & 1)) * 16))

// ---------------- embed / pool / router --------------------------------------
__global__ void gather_split_kernel(const int* __restrict__ ids,
                                    const float* __restrict__ emb)
{
    const int t = blockIdx.x;
    const int id = ids[t];
    const int c = threadIdx.x * 4;
    float4 v = *(const float4*)(emb + (size_t)id * ND + c);
    __nv_bfloat16 h0, h1, h2, h3, l0, l1, l2, l3;
    split2(v.x, h0, l0); split2(v.y, h1, l1);
    split2(v.z, h2, l2); split2(v.w, h3, l3);
    *(uint2*)(g_Xh + (size_t)t * ND + c) = make_uint2(pkbf(h0, h1), pkbf(h2, h3));
    *(uint2*)(g_Xl + (size_t)t * ND + c) = make_uint2(pkbf(l0, l1), pkbf(l2, l3));
}

__global__ void pool_partial_kernel(const int* __restrict__ ids,
                                    const float* __restrict__ emb)
{
    __shared__ int sid[128];
    const int t0 = blockIdx.x * 128;
    if (threadIdx.x < 128) sid[threadIdx.x] = ids[t0 + threadIdx.x];
    __syncthreads();
    const int c = threadIdx.x * 4;
    float4 s = make_float4(0.f, 0.f, 0.f, 0.f);
    for (int t = 0; t < 128; ++t) {
        const float4 v = *(const float4*)(emb + (size_t)sid[t] * ND + c);
        s.x += v.x; s.y += v.y; s.z += v.z; s.w += v.w;
    }
    *(float4*)(g_pool_part + blockIdx.x * ND + c) = s;
}

__global__ void pool_final_kernel()
{
    const int c = threadIdx.x * 4;
    float4 s = make_float4(0.f, 0.f, 0.f, 0.f);
    for (int b = 0; b < 64; ++b) {
        const float4 v = *(const float4*)(g_pool_part + b * ND + c);
        s.x += v.x; s.y += v.y; s.z += v.z; s.w += v.w;
    }
    const float inv = 1.0f / (float)NTOK;
    s.x *= inv; s.y *= inv; s.z *= inv; s.w *= inv;
    *(float4*)(g_pool + c) = s;
}

__global__ void router_kernel(const float* __restrict__ w_router)
{
    __shared__ float slog[NEXP];
    const int warp = threadIdx.x >> 5;
    const int lane = threadIdx.x & 31;
    float s = 0.f;
    for (int d = lane; d < ND; d += 32)
        s += g_pool[d] * w_router[d * NEXP + warp];
    #pragma unroll
    for (int o = 16; o > 0; o >>= 1) s += __shfl_down_sync(0xffffffffu, s, o);
    if (lane == 0) slog[warp] = s;
    __syncthreads();
    if (threadIdx.x == 0) {
        float v0 = -1e30f, v1 = -1e30f; int i0 = 0, i1 = 0;
        for (int n = 0; n < NEXP; ++n) {
            const float l = slog[n];
            if (l > v0) { v1 = v0; i1 = i0; v0 = l; i0 = n; }
            else if (l > v1) { v1 = l; i1 = n; }
        }
        const float e1  = expf(v1 - v0);
        const float den = 1.0f + e1;
        g_eidx[0] = i0; g_eidx[1] = i1;
        g_ewt[0] = 1.0f / den; g_ewt[1] = e1 / den;
    }
}

// ---------------- weight transpose + split ------------------------------------
__global__ void transpose_split_kernel(const float* __restrict__ src,
                                       int K, int N, long src_z, int mode)
{
    __shared__ float tile[32][33];
    const int e = blockIdx.z;
    __nv_bfloat16 *dh, *dl; long dst_z; int ld; int use_e;
    if (mode == 0)      { dh = g_w1h; dl = g_w1l; dst_z = (long)NH * ND; ld = ND;   use_e = 1; }
    else if (mode == 1) { dh = g_w2h; dl = g_w2l; dst_z = NH;            ld = KCAT; use_e = 1; }
    else                { dh = g_whh; dl = g_whl; dst_z = 0;             ld = ND;   use_e = 0; }

    const int sel = use_e ? g_eidx[e] : e;
    const float* in = src + (size_t)sel * src_z;
    dh += (size_t)e * dst_z;
    dl += (size_t)e * dst_z;

    const int n0 = blockIdx.x * 32, k0 = blockIdx.y * 32;
    const int tx = threadIdx.x, ty = threadIdx.y;   // (32, 8)
    #pragma unroll
    for (int j = 0; j < 32; j += 8)
        tile[ty + j][tx] = in[(size_t)(k0 + ty + j) * N + n0 + tx];
    __syncthreads();
    #pragma unroll
    for (int j = 0; j < 32; j += 8) {
        const float v = tile[tx][ty + j];
        __nv_bfloat16 h, l; split2(v, h, l);
        const size_t o = (size_t)(n0 + ty + j) * ld + k0 + tx;
        dh[o] = h; dl[o] = l;
    }
}

// ---------------- bf16-split mma.sync GEMM, 4-stage, 2 CTAs/SM -----------------
#define BM 128
#define BN 128
#define BK 16
#define NSTAGE 4
// per-stage: AH[128x32B] AL BH[128x32B] BL
#define OFF_AL 4096
#define OFF_BH 8192
#define OFF_BL 12288
#define STAGE  16384
#define SMEM_BYTES (NSTAGE * STAGE)   // 65536

// MODE 0: H = gelu(X @ w1t[e]^T)*wt[e] -> Hh/Hl   (grid.z = expert)
// MODE 1: O = H @ w2t^T -> Oh/Ol
// MODE 2: LOGITS = O @ wht^T -> fp32 out
template<int MODE>
__global__ void __launch_bounds__(256, 2)
mma_gemm_kernel(float* __restrict__ Cext)
{
    constexpr int K   = (MODE == 1) ? KCAT : ND;
    constexpr int NT  = K / BK;
    constexpr int LDC = (MODE == 0) ? KCAT : ((MODE == 1) ? ND : NV);

    const __nv_bfloat16 *Ah, *Al, *Bh_, *Bl_;
    if (MODE == 0)      { Ah = g_Xh; Al = g_Xl; Bh_ = g_w1h; Bl_ = g_w1l; }
    else if (MODE == 1) { Ah = g_Hh; Al = g_Hl; Bh_ = g_w2h; Bl_ = g_w2l; }
    else                { Ah = g_Oh; Al = g_Ol; Bh_ = g_whh; Bl_ = g_whl; }

    extern __shared__ __align__(16) uint8_t smraw[];
    const uint32_t smb = s2u(smraw);

    const int tid  = threadIdx.x;
    const int w    = tid >> 5, lane = tid & 31;
    const int g    = lane >> 2, tig = lane & 3;
    const int mb   = (w >> 2) * 64;        // 2 m-warps
    const int nb   = (w & 3) * 32;         // 4 n-warps
    const int bm   = blockIdx.y * BM;
    const int bn   = blockIdx.x * BN;

    float wt = 1.f; int ccol0 = bn;
    if (MODE == 0) {
        const int e = blockIdx.z;
        wt    = g_ewt[e];
        Bh_  += (size_t)e * NH * ND;
        Bl_  += (size_t)e * NH * ND;
        ccol0 = e * NH + bn;
    }

    const __nv_bfloat16* Ab_h = Ah + (size_t)bm * K;
    const __nv_bfloat16* Ab_l = Al + (size_t)bm * K;
    const __nv_bfloat16* Bb_h = Bh_ + (size_t)bn * K;
    const __nv_bfloat16* Bb_l = Bl_ + (size_t)bn * K;

    // fill: 1024 16B chunks / 256 threads = 4 each (one per region)
    auto fill = [&](uint32_t sbase, int k0) {
        const int ci = tid;
        const size_t go = (size_t)(ci >> 1) * K + k0 + (ci & 1) * 8;
        CPASYNC16(sbase + SWZ16(ci),          Ab_h + go);
        CPASYNC16(sbase + OFF_AL + SWZ16(ci), Ab_l + go);
        CPASYNC16(sbase + OFF_BH + SWZ16(ci), Bb_h + go);
        CPASYNC16(sbase + OFF_BL + SWZ16(ci), Bb_l + go);
    };

    // ldmatrix lane offsets (verified mapping from round 5)
    const int am = lane >> 3;
    const int a_ci0 = (mb + ((am & 1) << 3) + (lane & 7)) * 2 + (am >> 1);
    const uint32_t aoff = SWZ16(a_ci0);
    const int bmm = lane >> 3;
    const int b_ci0 = (nb + ((bmm >> 1) << 3) + (lane & 7)) * 2 + (bmm & 1);
    const uint32_t boff = SWZ16(b_ci0);

    float acc[4][4][4];
    #pragma unroll
    for (int i = 0; i < 4; ++i)
        #pragma unroll
        for (int j = 0; j < 4; ++j)
            #pragma unroll
            for (int q = 0; q < 4; ++q) acc[i][j][q] = 0.f;

    // prologue: stages 0,1,2 in flight
    fill(smb, 0);              CPCOMMIT();
    fill(smb + STAGE, BK);     CPCOMMIT();
    fill(smb + 2 * STAGE, 2 * BK); CPCOMMIT();

    int rd = 0, wr = 3;
    #pragma unroll 1
    for (int t = 0; t < NT; ++t) {
        CPWAIT2();
        __syncthreads();

        const uint32_t sb = smb + rd * STAGE;

        // B fragments (4 n-tiles, hi+lo)
        uint32_t Bhf[4][2], Blf[4][2];
        #pragma unroll
        for (int p = 0; p < 2; ++p) {
            uint32_t r0, r1, r2, r3;
            LDSM4(r0, r1, r2, r3, sb + OFF_BH + boff + p * 512);
            Bhf[2*p][0] = r0; Bhf[2*p][1] = r1;
            Bhf[2*p+1][0] = r2; Bhf[2*p+1][1] = r3;
            LDSM4(r0, r1, r2, r3, sb + OFF_BL + boff + p * 512);
            Blf[2*p][0] = r0; Blf[2*p][1] = r1;
            Blf[2*p+1][0] = r2; Blf[2*p+1][1] = r3;
        }

        if (t + 3 < NT) fill(smb + wr * STAGE, (t + 3) * BK);
        CPCOMMIT();

        #pragma unroll
        for (int mt = 0; mt < 4; ++mt) {
            uint32_t Ahf[4], Alf[4];
            LDSM4(Ahf[0], Ahf[1], Ahf[2], Ahf[3], sb + aoff + mt * 512);
            LDSM4(Alf[0], Alf[1], Alf[2], Alf[3], sb + OFF_AL + aoff + mt * 512);
            #pragma unroll
            for (int nt = 0; nt < 4; ++nt) {
                mma_bf16(acc[mt][nt], Ahf, Bhf[nt]);
                mma_bf16(acc[mt][nt], Ahf, Blf[nt]);
                mma_bf16(acc[mt][nt], Alf, Bhf[nt]);
            }
        }

        rd = (rd + 1) & 3;
        wr = (wr + 1) & 3;
    }

    // ---- epilogue ----
    #pragma unroll
    for (int mt = 0; mt < 4; ++mt) {
        const int row0 = bm + mb + mt * 16 + g;
        #pragma unroll
        for (int rr = 0; rr < 2; ++rr) {
            const int row = row0 + rr * 8;
            const size_t base = (size_t)row * LDC + ccol0 + nb + 2 * tig;
            #pragma unroll
            for (int nt = 0; nt < 4; ++nt) {
                float v0 = acc[mt][nt][2 * rr];
                float v1 = acc[mt][nt][2 * rr + 1];
                if (MODE == 0) {
                    v0 = gelu_tanh(v0) * wt;
                    v1 = gelu_tanh(v1) * wt;
                }
                if (MODE == 2) {
                    *(float2*)(Cext + base + nt * 8) = make_float2(v0, v1);
                } else {
                    __nv_bfloat16 h0, l0, h1, l1;
                    split2(v0, h0, l0); split2(v1, h1, l1);
                    __nv_bfloat16* dh = (MODE == 0) ? g_Hh : g_Oh;
                    __nv_bfloat16* dl = (MODE == 0) ? g_Hl : g_Ol;
                    *(uint32_t*)(dh + base + nt * 8) = pkbf(h0, h1);
                    *(uint32_t*)(dl + base + nt * 8) = pkbf(l0, l1);
                }
            }
        }
    }
}

// ---------------- entry point -------------------------------------------------
extern "C" void kernel_launch(void* const* d_in, const int* in_sizes, int n_in,
                              void* d_out, int out_size)
{
    (void)in_sizes; (void)n_in; (void)out_size;
    const int*   ids = (const int*)  d_in[0];
    const float* emb = (const float*)d_in[1];
    const float* wr  = (const float*)d_in[2];
    const float* w1  = (const float*)d_in[3];
    const float* w2  = (const float*)d_in[4];
    const float* wh  = (const float*)d_in[5];
    float* out = (float*)d_out;

    cudaFuncSetAttribute(mma_gemm_kernel<0>, cudaFuncAttributeMaxDynamicSharedMemorySize, SMEM_BYTES);
    cudaFuncSetAttribute(mma_gemm_kernel<1>, cudaFuncAttributeMaxDynamicSharedMemorySize, SMEM_BYTES);
    cudaFuncSetAttribute(mma_gemm_kernel<2>, cudaFuncAttributeMaxDynamicSharedMemorySize, SMEM_BYTES);

    gather_split_kernel<<<NTOK, 256>>>(ids, emb);
    pool_partial_kernel<<<64,   256>>>(ids, emb);
    pool_final_kernel  <<<1,    256>>>();
    router_kernel      <<<1,    512>>>(wr);

    transpose_split_kernel<<<dim3(NH / 32, ND / 32, 2), dim3(32, 8)>>>(w1, ND, NH, (long)ND * NH, 0);
    transpose_split_kernel<<<dim3(ND / 32, NH / 32, 2), dim3(32, 8)>>>(w2, NH, ND, (long)NH * ND, 1);
    transpose_split_kernel<<<dim3(NV / 32, ND / 32, 1), dim3(32, 8)>>>(wh, ND, NV, 0, 2);

    mma_gemm_kernel<0><<<dim3(NH / BN, NTOK / BM, 2), 256, SMEM_BYTES>>>(nullptr);
    mma_gemm_kernel<1><<<dim3(ND / BN, NTOK / BM, 1), 256, SMEM_BYTES>>>(nullptr);
    mma_gemm_kernel<2><<<dim3(NV / BN, NTOK / BM, 1), 256, SMEM_BYTES>>>(out);
}